// round 2
// baseline (speedup 1.0000x reference)
#include <cuda_runtime.h>
#include <cuda_bf16.h>
#include <math.h>

// ---------------- constants ----------------
#define BATCH 32
#define C 80
#define F 2048
#define HW 1024
#define HID 256
#define EDD 64
#define EIN 259            // 4*EDD + 3
#define TEMP_INV 0.4f      // 1/2.5
#define BETA_POS 0.5f
#define GAMMA_NEG 0.25f

// output offsets (flat concat of tuple: W_adj, aw, dlog, cam_vis, refined, total)
#define OUT_WADJ 0
#define OUT_AW   (C*C)                       // 6400
#define OUT_DLOG (OUT_AW + C*F)              // 170240
#define OUT_CAM  (OUT_DLOG + C)              // 170320
#define OUT_REF  (OUT_CAM + BATCH*C*HW)      // 2791760
#define OUT_TOT  (OUT_REF + BATCH*C)         // 2794320

// ---------------- scratch ----------------
struct Scratch {
    float pooled[BATCH*F];
    float probs[BATCH*C];
    float yv[BATCH*C];
    float wsum[C];
    float freq[C];
    float Pb[BATCH];
    float present[C];
    float proto[C*F];
    float nrm[C];
    float cosm[C*C];
    float t1[C*HID];
    float Hn[C*HID];
    float Zd[C*EDD];
    float r[C*C];
    float Wadj[C*C];
    float Amat[C*C];
    float AZ[C*HID];
    float msgt[C*HID];
    float Z[C*HID];
    float dlog[C];
    float lossbuf[4];
    float cam[(size_t)BATCH*C*HW];
};
__device__ Scratch g_s;

__device__ __forceinline__ float sigm(float x){ return 1.f/(1.f+expf(-x)); }
__device__ __forceinline__ float softplusf(float x){ return fmaxf(x,0.f)+log1pf(expf(-fabsf(x))); }
__device__ __forceinline__ float bcef(float h,float t){ return fmaxf(h,0.f)-h*t+log1pf(expf(-fabsf(h))); }

// packed f32x2 helpers (FFMA2 — 2x fp32 FMA throughput, sm_103a)
__device__ __forceinline__ unsigned long long packf2(float lo, float hi){
    unsigned long long r;
    asm("mov.b64 %0, {%1, %2};" : "=l"(r) : "f"(lo), "f"(hi));
    return r;
}
__device__ __forceinline__ void fmaf2(unsigned long long &acc, unsigned long long a, unsigned long long b){
    asm("fma.rn.f32x2 %0, %1, %2, %0;" : "+l"(acc) : "l"(a), "l"(b));
}
__device__ __forceinline__ float2 unpackf2(unsigned long long v){
    float2 f;
    asm("mov.b64 {%0, %1}, %2;" : "=f"(f.x), "=f"(f.y) : "l"(v));
    return f;
}

// ---------------- kernels ----------------

// pooled[b,f] = mean over 1024 pixels. one warp per row.
__global__ void k_pooled(const float* __restrict__ feats, float* __restrict__ pooled){
    int row = blockIdx.x*8 + (threadIdx.x>>5);
    if (row >= BATCH*F) return;
    int lane = threadIdx.x & 31;
    const float4* p = (const float4*)(feats + (size_t)row*HW);
    float s = 0.f;
    #pragma unroll
    for (int i=0;i<8;i++){ float4 v = p[lane + i*32]; s += (v.x+v.y)+(v.z+v.w); }
    #pragma unroll
    for (int o=16;o>0;o>>=1) s += __shfl_down_sync(0xffffffffu,s,o);
    if (lane==0) pooled[row] = s * (1.f/HW);
}

__global__ void k_small(const float* __restrict__ logits, const int* __restrict__ labels){
    int t = threadIdx.x;
    for (int i=t;i<BATCH*C;i+=256){
        float p = sigm(logits[i]);
        g_s.probs[i]=p;
        g_s.yv[i]=fmaxf((float)labels[i],0.f);
    }
    __syncthreads();
    if (t<C){
        float s=0.f, pr=0.f;
        for (int b=0;b<BATCH;b++){ s+=g_s.probs[b*C+t]; pr=fmaxf(pr,g_s.yv[b*C+t]); }
        g_s.wsum[t]=fmaxf(s,1e-6f); g_s.freq[t]=s*(1.f/BATCH);
        g_s.present[t]= pr>0.f ? 1.f : 0.f;
    }
    if (t>=128 && t<128+BATCH){
        int b=t-128; float s=0.f;
        for (int c=0;c<C;c++) s+=g_s.probs[b*C+c];
        g_s.Pb[b]=s;
    }
}

// proto[c,f] = sum_b probs[b,c]*pooled[b,f] / wsum[c];  grid(C, F/256)
__global__ void k_proto(){
    int c = blockIdx.x;
    int f = blockIdx.y*256 + threadIdx.x;
    __shared__ float pc[BATCH];
    if (threadIdx.x < BATCH) pc[threadIdx.x] = g_s.probs[threadIdx.x*C + c];
    __syncthreads();
    float s=0.f;
    #pragma unroll 8
    for (int b=0;b<BATCH;b++) s += pc[b]*g_s.pooled[b*F+f];
    g_s.proto[c*F+f] = s / g_s.wsum[c];
}

__global__ void k_norm(){
    int c = blockIdx.x; int t = threadIdx.x;
    __shared__ float red[256];
    float s=0.f;
    for (int k=t;k<F;k+=256){ float v=g_s.proto[c*F+k]; s+=v*v; }
    red[t]=s; __syncthreads();
    for (int o=128;o>0;o>>=1){ if(t<o) red[t]+=red[t+o]; __syncthreads(); }
    if (t==0) g_s.nrm[c] = fmaxf(sqrtf(red[0]),1e-6f);
}

// cos[i,j] = clip(dot(proto_i,proto_j)/(ni*nj), -1, 1); block per i, warp per j
__global__ void k_cos(){
    int i = blockIdx.x;
    __shared__ float si[F];
    for (int k=threadIdx.x;k<F;k+=256) si[k]=g_s.proto[i*F+k];
    __syncthreads();
    int w = threadIdx.x>>5, lane = threadIdx.x&31;
    float ni = g_s.nrm[i];
    for (int j=w;j<C;j+=8){
        const float* pj = g_s.proto + (size_t)j*F;
        float s=0.f;
        for (int k=lane;k<F;k+=32) s += si[k]*pj[k];
        #pragma unroll
        for (int o=16;o>0;o>>=1) s += __shfl_down_sync(0xffffffffu,s,o);
        if (lane==0){
            float v = s/(ni*g_s.nrm[j]);
            g_s.cosm[i*C+j] = fminf(fmaxf(v,-1.f),1.f);
        }
    }
}

// out[m,j] = act( (res?res[m,j]:0) + bias[j] + sum_k X[m,k]*W[k,j] )
// 8 rows per block (weight matrix read once per 8 rows). blockDim = N (<=256).
// dyn smem = 8*K floats.
__global__ void k_lin(const float* __restrict__ X, const float* __restrict__ W,
                      const float* __restrict__ bias, const float* __restrict__ res,
                      float* __restrict__ out, int K, int N, int act){
    extern __shared__ float sx[];
    int m0 = blockIdx.x*8;
    for (int l=threadIdx.x; l<8*K; l+=blockDim.x) sx[l]=X[(size_t)m0*K+l];
    __syncthreads();
    int j = threadIdx.x;
    if (j>=N) return;
    float acc[8];
    float bv = bias ? bias[j] : 0.f;
    #pragma unroll
    for (int r=0;r<8;r++) acc[r]=bv;
    for (int k=0;k<K;k++){
        float w = W[(size_t)k*N+j];
        #pragma unroll
        for (int r=0;r<8;r++) acc[r] += sx[r*K+k]*w;
    }
    #pragma unroll
    for (int r=0;r<8;r++){
        float a = acc[r];
        if (res) a += res[(size_t)(m0+r)*N+j];
        if (act) a = fmaxf(a,0.f);
        out[(size_t)(m0+r)*N+j] = a;
    }
}

// edge MLP: r[i,j]. grid(80,4), 256 threads, 2 edges in flight, weights in smem.
__global__ void k_edge(const float* __restrict__ w1, const float* __restrict__ b1,
                       const float* __restrict__ w2, const float* __restrict__ b2,
                       const float* __restrict__ w3, const float* __restrict__ b3){
    extern __shared__ float sm[];
    float* sw1 = sm;                 // 259*128
    float* sw2 = sw1 + EIN*128;      // 128*64
    float* sw3 = sw2 + 128*64;       // 64
    float* sb1 = sw3 + 64;           // 128
    float* sb2 = sb1 + 128;          // 64
    float* szi = sb2 + 64;           // 64
    float* sfeat = szi + 64;         // 2*259
    float* sh1 = sfeat + 2*EIN;      // 2*128
    float* sh2 = sh1 + 256;          // 2*64
    int tid = threadIdx.x;
    for (int i=tid;i<EIN*128;i+=256) sw1[i]=w1[i];
    for (int i=tid;i<128*64;i+=256)  sw2[i]=w2[i];
    if (tid<64)  sw3[tid]=w3[tid];
    if (tid<128) sb1[tid]=b1[tid];
    if (tid<64)  sb2[tid]=b2[tid];
    int iRow = blockIdx.x;
    if (tid<64) szi[tid]=g_s.Zd[iRow*EDD+tid];
    float b3v = b3[0];
    float fi = g_s.freq[iRow];
    __syncthreads();
    int g = tid>>7, lt = tid&127;
    int jbase = blockIdx.y*20;
    for (int step=0;step<10;step++){
        int j = jbase + step*2 + g;
        float* feat = sfeat + g*EIN;
        if (lt<64){
            float zi = szi[lt];
            float zj = g_s.Zd[j*EDD+lt];
            feat[lt]      = zi;
            feat[64+lt]   = zj;
            feat[128+lt]  = fabsf(zi-zj);
            feat[192+lt]  = zi*zj;
        } else if (lt==64){
            feat[256] = g_s.cosm[iRow*C+j];
            feat[257] = fi;
            feat[258] = g_s.freq[j];
        }
        __syncthreads();
        {   // layer1: out neuron = lt
            float a0=0.f,a1=0.f;
            for (int k=0;k+1<EIN;k+=2){
                a0 += feat[k  ]*sw1[(k  )*128+lt];
                a1 += feat[k+1]*sw1[(k+1)*128+lt];
            }
            a0 += feat[258]*sw1[258*128+lt];
            sh1[g*128+lt] = fmaxf(a0+a1+sb1[lt],0.f);
        }
        __syncthreads();
        if (lt<64){
            float a0=0.f,a1=0.f;
            for (int k=0;k<128;k+=2){
                a0 += sh1[g*128+k  ]*sw2[(k  )*64+lt];
                a1 += sh1[g*128+k+1]*sw2[(k+1)*64+lt];
            }
            sh2[g*64+lt] = fmaxf(a0+a1+sb2[lt],0.f);
        }
        __syncthreads();
        if (lt<32){
            float v = sh2[g*64+lt]*sw3[lt] + sh2[g*64+32+lt]*sw3[32+lt];
            #pragma unroll
            for (int o=16;o>0;o>>=1) v += __shfl_down_sync(0xffffffffu,v,o);
            if (lt==0) g_s.r[iRow*C+j] = v + b3v;
        }
        __syncthreads();
    }
}

// single block: W_adj, A, edge losses, sparsity
__global__ void k_graph(const float* __restrict__ prior, float* __restrict__ out){
    __shared__ float sW[C*C];
    __shared__ float rs[C];
    __shared__ float red[256];
    __shared__ float params[2];
    int t = threadIdx.x;
    for (int idx=t; idx<C*C; idx+=256){
        int i=idx/C, j=idx%C;
        float hij = prior[idx]*TEMP_INV + g_s.r[idx];
        float hji = prior[j*C+i]*TEMP_INV + g_s.r[j*C+i];
        float w = 0.5f*(sigm(hij)+sigm(hji));
        if (i==j) w=0.f;
        sW[idx]=w; g_s.Wadj[idx]=w; out[OUT_WADJ+idx]=w;
    }
    __syncthreads();
    if (t<C){ float s=0.f; for (int j=0;j<C;j++) s+=sW[t*C+j]; rs[t]=fmaxf(s,1e-6f); }
    __syncthreads();
    for (int idx=t; idx<C*C; idx+=256) g_s.Amat[idx]=sW[idx]/rs[idx/C];
    float aP=0.f,aN=0.f,aE=0.f;
    for (int idx=t; idx<C*C; idx+=256){
        int i=idx/C, j=idx%C;
        float em = (i!=j && g_s.present[i]>0.f && g_s.present[j]>0.f)?1.f:0.f;
        float tv = sigm(prior[idx]*TEMP_INV);
        float pf = tv>0.5f?1.f:0.f;
        aP+=pf*em; aN+=(1.f-pf)*em; aE+=em;
    }
    red[t]=aP; __syncthreads();
    for (int o=128;o>0;o>>=1){ if(t<o) red[t]+=red[t+o]; __syncthreads(); }
    float nP = fmaxf(red[0],1.f); __syncthreads();
    red[t]=aN; __syncthreads();
    for (int o=128;o>0;o>>=1){ if(t<o) red[t]+=red[t+o]; __syncthreads(); }
    float nN = fmaxf(red[0],1.f); __syncthreads();
    red[t]=aE; __syncthreads();
    for (int o=128;o>0;o>>=1){ if(t<o) red[t]+=red[t+o]; __syncthreads(); }
    if (t==0){
        params[0] = fminf(fmaxf(nN/nP,1.f),10.f);
        params[1] = fmaxf(red[0],1.f);
    }
    __syncthreads();
    float wpos = params[0], nedges = params[1];
    float aL=0.f,aR=0.f,aS=0.f;
    for (int idx=t; idx<C*C; idx+=256){
        int i=idx/C, j=idx%C;
        float em = (i!=j && g_s.present[i]>0.f && g_s.present[j]>0.f)?1.f:0.f;
        float tv = sigm(prior[idx]*TEMP_INV);
        float h  = prior[idx]*TEMP_INV + g_s.r[idx];
        float wgt = (tv>0.5f)? wpos : 1.f;
        aL += bcef(h,tv)*wgt*em;
        aR += fabsf(g_s.r[idx])*em;
        aS += sW[idx];
    }
    red[t]=aL; __syncthreads();
    for (int o=128;o>0;o>>=1){ if(t<o) red[t]+=red[t+o]; __syncthreads(); }
    float SL = red[0]; __syncthreads();
    red[t]=aR; __syncthreads();
    for (int o=128;o>0;o>>=1){ if(t<o) red[t]+=red[t+o]; __syncthreads(); }
    float SR = red[0]; __syncthreads();
    red[t]=aS; __syncthreads();
    for (int o=128;o>0;o>>=1){ if(t<o) red[t]+=red[t+o]; __syncthreads(); }
    if (t==0){
        g_s.lossbuf[0]=SL/nedges;
        g_s.lossbuf[1]=0.001f*SR/nedges;
        g_s.lossbuf[2]=red[0]/(float)(C*C);
    }
}

// aw (softplus + row-normalize) + dlog. 8 classes per block (grid 10).
__global__ void k_aw(const float* __restrict__ alpha_w, const float* __restrict__ alpha_b,
                     const float* __restrict__ bias_w, const float* __restrict__ bias_b,
                     float* __restrict__ out){
    int c0 = blockIdx.x*8, t = threadIdx.x;
    __shared__ float z[8][HID];
    __shared__ float red[256];
    __shared__ float invs[8];
    for (int l=t; l<8*HID; l+=256) z[l>>8][l&255] = g_s.Z[(size_t)(c0+(l>>8))*HID + (l&255)];
    __syncthreads();
    float vals[8][8];
    float lsum[8];
    #pragma unroll
    for (int cls=0;cls<8;cls++) lsum[cls]=0.f;
    for (int it=0;it<8;it++){
        int j = it*256 + t;
        float acc[8];
        #pragma unroll
        for (int cls=0;cls<8;cls++) acc[cls]=0.f;
        for (int k=0;k<HID;k++){
            float w = alpha_w[(size_t)k*F+j];
            #pragma unroll
            for (int cls=0;cls<8;cls++) acc[cls] += z[cls][k]*w;
        }
        float ab = alpha_b[j];
        #pragma unroll
        for (int cls=0;cls<8;cls++){
            float sp = softplusf(acc[cls]+ab);
            vals[cls][it]=sp; lsum[cls]+=sp;
        }
    }
    for (int cls=0;cls<8;cls++){
        red[t]=lsum[cls]; __syncthreads();
        for (int o=128;o>0;o>>=1){ if(t<o) red[t]+=red[t+o]; __syncthreads(); }
        if (t==0) invs[cls] = 1.f/fmaxf(red[0],1e-6f);
        __syncthreads();
    }
    #pragma unroll
    for (int cls=0;cls<8;cls++){
        float inv = invs[cls];
        #pragma unroll
        for (int it=0;it<8;it++)
            out[OUT_AW + (size_t)(c0+cls)*F + it*256 + t] = vals[cls][it]*inv;
    }
    float bw = bias_w[t&255];
    for (int cls=0;cls<8;cls++){
        red[t] = z[cls][t]*bw; __syncthreads();
        for (int o=128;o>0;o>>=1){ if(t<o) red[t]+=red[t+o]; __syncthreads(); }
        if (t==0){ float d = red[0]+bias_b[0]; g_s.dlog[c0+cls]=d; out[OUT_DLOG+c0+cls]=d; }
        __syncthreads();
    }
}

// refined + cls_loss + total. single block.
__global__ void k_refined(const float* __restrict__ logits, const int* __restrict__ labels,
                          float* __restrict__ out){
    __shared__ float sW[C*C];
    __shared__ float sq[BATCH*C];
    __shared__ float red[256];
    int t = threadIdx.x;
    for (int i=t;i<C*C;i+=256) sW[i]=g_s.Wadj[i];
    for (int i=t;i<BATCH*C;i+=256) sq[i]=g_s.probs[i]*g_s.yv[i];
    __syncthreads();
    float accL=0.f, accM=0.f;
    for (int idx=t; idx<BATCH*C; idx+=256){
        int b=idx/C, d=idx%C;
        float s=0.f;
        for (int c=0;c<C;c++) s += sq[b*C+c]*sW[c*C+d];
        float pos = g_s.yv[idx]*s;
        float neg = g_s.Pb[b] - pos;
        float ref = logits[idx] + BETA_POS*pos - GAMMA_NEG*neg + g_s.dlog[d];
        out[OUT_REF+idx] = ref;
        float lab = (float)labels[idx];
        float mflag = (lab != -1.f) ? 1.f : 0.f;
        float safe_t = (mflag>0.f)? lab : 0.f;
        accL += bcef(ref,safe_t)*mflag;
        accM += mflag;
    }
    red[t]=accL; __syncthreads();
    for (int o=128;o>0;o>>=1){ if(t<o) red[t]+=red[t+o]; __syncthreads(); }
    float SL=red[0]; __syncthreads();
    red[t]=accM; __syncthreads();
    for (int o=128;o>0;o>>=1){ if(t<o) red[t]+=red[t+o]; __syncthreads(); }
    if (t==0){
        float cls = SL/fmaxf(red[0],1.f);
        out[OUT_TOT] = cls + 0.1f*g_s.lossbuf[0] + g_s.lossbuf[1] + 0.01f*g_s.lossbuf[2];
    }
}

// cam GEMM: cam[b,:,n-tile] = aw[80,2048] @ feats[b,2048,n-tile].
// BM=80 (whole M), BN=128, BK=32 -> feats read exactly once.
// 256 threads: tm=tid>>4 (5 rows each), tn=tid&15 (8 strided cols each).
// f32x2 packed FMA for 2x fp32 throughput.
__global__ void k_cam(const float* __restrict__ feats, const float* __restrict__ aw){
    __shared__ float As[C][32];      // As[m][k]
    __shared__ float Bs[32][128];    // Bs[k][n]
    int tid = threadIdx.x;
    int tn = tid & 15;
    int tm = tid >> 4;
    int nbase = blockIdx.x * 128;
    int b = blockIdx.y;
    const float* Bp = feats + (size_t)b*F*HW + nbase;
    unsigned long long acc[5][4];
    #pragma unroll
    for (int i=0;i<5;i++)
        #pragma unroll
        for (int j=0;j<4;j++) acc[i][j]=0ull;
    for (int k0=0;k0<F;k0+=32){
        for (int l=tid; l<C*32; l+=256){
            int m=l>>5, k=l&31;
            As[m][k] = aw[(size_t)m*F + k0 + k];
        }
        #pragma unroll
        for (int r=0;r<4;r++){
            int kk = r*8 + (tid>>5);
            int c4 = tid&31;
            *(float4*)&Bs[kk][c4*4] = *(const float4*)(Bp + (size_t)(k0+kk)*HW + c4*4);
        }
        __syncthreads();
        #pragma unroll
        for (int kk=0;kk<32;kk++){
            unsigned long long b2[4];
            #pragma unroll
            for (int j=0;j<4;j++)
                b2[j] = packf2(Bs[kk][tn+32*j], Bs[kk][tn+16+32*j]);
            #pragma unroll
            for (int i=0;i<5;i++){
                float av = As[tm*5+i][kk];
                unsigned long long a2 = packf2(av,av);
                #pragma unroll
                for (int j=0;j<4;j++) fmaf2(acc[i][j], a2, b2[j]);
            }
        }
        __syncthreads();
    }
    #pragma unroll
    for (int i=0;i<5;i++){
        int m = tm*5+i;
        float* dst = g_s.cam + ((size_t)b*C+m)*HW + nbase;
        #pragma unroll
        for (int j=0;j<4;j++){
            float2 v = unpackf2(acc[i][j]);
            dst[tn+32*j]    = v.x;
            dst[tn+16+32*j] = v.y;
        }
    }
}

// relu + per-(b,c) min/max normalize. block per row.
__global__ void k_minmax(float* __restrict__ out){
    __shared__ float rmn[256], rmx[256];
    int row = blockIdx.x, t = threadIdx.x;
    const float* base = g_s.cam + (size_t)row*HW;
    float v[4]; float mn=3.4e38f, mx=-3.4e38f;
    #pragma unroll
    for (int i=0;i<4;i++){
        v[i]=fmaxf(base[t+i*256],0.f);
        mn=fminf(mn,v[i]); mx=fmaxf(mx,v[i]);
    }
    rmn[t]=mn; rmx[t]=mx; __syncthreads();
    for (int o=128;o>0;o>>=1){
        if (t<o){ rmn[t]=fminf(rmn[t],rmn[t+o]); rmx[t]=fmaxf(rmx[t],rmx[t+o]); }
        __syncthreads();
    }
    mn=rmn[0]; mx=rmx[0];
    float inv = 1.f/(mx-mn+1e-6f);
    #pragma unroll
    for (int i=0;i<4;i++)
        out[OUT_CAM + (size_t)row*HW + t + i*256] = (v[i]-mn)*inv;
}

// ---------------- launch ----------------
extern "C" void kernel_launch(void* const* d_in, const int* in_sizes, int n_in,
                              void* d_out, int out_size){
    const float* feats   = (const float*)d_in[0];
    const float* logits  = (const float*)d_in[1];
    const int*   labels  = (const int*)d_in[2];
    const float* prior   = (const float*)d_in[3];
    const float* pp_w1   = (const float*)d_in[4];
    const float* pp_b1   = (const float*)d_in[5];
    const float* pp_w2   = (const float*)d_in[6];
    const float* pp_b2   = (const float*)d_in[7];
    const float* msg_w1  = (const float*)d_in[8];
    const float* msg_b1  = (const float*)d_in[9];
    const float* msg_w2  = (const float*)d_in[10];
    const float* msg_b2  = (const float*)d_in[11];
    const float* ed_w    = (const float*)d_in[12];
    const float* ed_b    = (const float*)d_in[13];
    const float* em_w1   = (const float*)d_in[14];
    const float* em_b1   = (const float*)d_in[15];
    const float* em_w2   = (const float*)d_in[16];
    const float* em_b2   = (const float*)d_in[17];
    const float* em_w3   = (const float*)d_in[18];
    const float* em_b3   = (const float*)d_in[19];
    const float* alpha_w = (const float*)d_in[20];
    const float* alpha_b = (const float*)d_in[21];
    const float* bias_w  = (const float*)d_in[22];
    const float* bias_b  = (const float*)d_in[23];
    float* out = (float*)d_out;

    void* sp = 0;
    cudaGetSymbolAddress(&sp, g_s);
    Scratch* S = (Scratch*)sp;

    size_t edge_smem = (size_t)(EIN*128 + 128*64 + 64 + 128 + 64 + 64 + 2*EIN + 2*128 + 2*64) * sizeof(float);
    cudaFuncSetAttribute(k_edge, cudaFuncAttributeMaxDynamicSharedMemorySize, (int)edge_smem);
    cudaFuncSetAttribute(k_lin, cudaFuncAttributeMaxDynamicSharedMemorySize, 8*F*(int)sizeof(float));

    k_pooled<<<(BATCH*F)/8, 256>>>(feats, S->pooled);
    k_small<<<1,256>>>(logits, labels);
    { dim3 g(C, F/256); k_proto<<<g,256>>>(); }
    k_norm<<<C,256>>>();
    k_cos<<<C,256>>>();
    // t1 = relu(proto @ pp_w1 + b1)            [80,2048]@[2048,256]
    k_lin<<<C/8, HID, 8*F*sizeof(float)>>>(S->proto, pp_w1, pp_b1, 0, S->t1, F, HID, 1);
    // Hn = t1 @ pp_w2 + b2                     [80,256]@[256,256]
    k_lin<<<C/8, HID, 8*HID*sizeof(float)>>>(S->t1, pp_w2, pp_b2, 0, S->Hn, HID, HID, 0);
    // Zd = relu(Hn @ ed_w + ed_b)              [80,256]@[256,64]
    k_lin<<<C/8, EDD, 8*HID*sizeof(float)>>>(S->Hn, ed_w, ed_b, 0, S->Zd, HID, EDD, 1);
    { dim3 g(C,4); k_edge<<<g,256,edge_smem>>>(em_w1, em_b1, em_w2, em_b2, em_w3, em_b3); }
    k_graph<<<1,256>>>(prior, out);
    // AZ = A @ Hn                              [80,80]@[80,256]
    k_lin<<<C/8, HID, 8*C*sizeof(float)>>>(S->Amat, S->Hn, 0, 0, S->AZ, C, HID, 0);
    // msgt = relu(AZ @ msg_w1 + b1)
    k_lin<<<C/8, HID, 8*HID*sizeof(float)>>>(S->AZ, msg_w1, msg_b1, 0, S->msgt, HID, HID, 1);
    // Z = relu(Hn + msgt @ msg_w2 + b2)
    k_lin<<<C/8, HID, 8*HID*sizeof(float)>>>(S->msgt, msg_w2, msg_b2, S->Hn, S->Z, HID, HID, 1);
    k_aw<<<C/8,256>>>(alpha_w, alpha_b, bias_w, bias_b, out);
    k_refined<<<1,256>>>(logits, labels, out);
    { dim3 g(HW/128, BATCH); k_cam<<<g,256>>>(feats, out + OUT_AW); }
    k_minmax<<<BATCH*C, 256>>>(out);

    (void)in_sizes; (void)n_in; (void)out_size;
}